// round 12
// baseline (speedup 1.0000x reference)
#include <cuda_runtime.h>

// ---------------------------------------------------------------------------
// MaskRemoval — R12: two kernels; raster folded into scan, zero co-resident.
//   k_main  : grid (NCLS + NW_ZERO). bid<NCLS: per-class suppression with
//             ON-THE-FLY warp-ballot rasterization (pass A count, pass B
//             merge) against an 80KB smem class mask; last scan CTA (ticket)
//             compacts -> g_po/g_nk/keep_inds. bid>=NCLS: zero-writer CTAs
//             streaming the 256MB energy tensor (hides the scan chain).
//   k_paste : grid (N,8). slot -> g_po[slot]; pure bilinear paste.
// ---------------------------------------------------------------------------

#define MAXN   128
#define NCLS   80
#define MM     28
#define IMG_H  800
#define IMG_W  800
#define WPR    25                      // 800/32 words per image row
#define BOXMAX 384
#define NSPLIT 8                       // paste y-slices per ROI
#define NW_ZERO 512                    // zero-writer CTAs in k_main
#define CMASK_BYTES (IMG_H * WPR * 4)  // 80000 B dynamic smem for k_main

__device__ int g_keep[MAXN];
__device__ int g_done = 0;                       // scan arrival ticket
__device__ int g_po[MAXN];                       // slot -> original roi idx
__device__ int g_nk;                             // number of kept slots

// exact reference bilinear form (keep decision thresholds on val>0)
__device__ __forceinline__ float bilin_ref(const float* lg, float sx, float sy) {
    int ix0 = (int)sx;
    int iy0 = (int)sy;
    int ix1 = min(ix0 + 1, MM - 1);
    int iy1 = min(iy0 + 1, MM - 1);
    float fx = sx - (float)ix0;
    float fy = sy - (float)iy0;
    float v00 = lg[iy0 * MM + ix0], v01 = lg[iy0 * MM + ix1];
    float v10 = lg[iy1 * MM + ix0], v11 = lg[iy1 * MM + ix1];
    return (1.0f - fy) * ((1.0f - fx) * v00 + fx * v01)
         +         fy  * ((1.0f - fx) * v10 + fx * v11);
}

// ---------------------------------------------------------------------------
__global__ __launch_bounds__(256) void k_main(const float* __restrict__ rois,
                                              const float* __restrict__ prob,
                                              const int*   __restrict__ clsidx,
                                              const float* __restrict__ mask_prob,
                                              float* __restrict__ out_keep,
                                              float4* __restrict__ energy4,
                                              long long n4, int N, int has_keep) {
    // ---- zero-writer CTAs ---------------------------------------------------
    if (blockIdx.x >= NCLS) {
        long long wid = blockIdx.x - NCLS;
        long long nthreads = (long long)NW_ZERO * blockDim.x;
        long long i = wid * blockDim.x + threadIdx.x;
        float4 z = make_float4(0.f, 0.f, 0.f, 0.f);
        long long s4 = 4 * nthreads;
        for (; i + 3 * nthreads < n4; i += s4) {
            __stcs(&energy4[i], z);
            __stcs(&energy4[i + nthreads], z);
            __stcs(&energy4[i + 2 * nthreads], z);
            __stcs(&energy4[i + 3 * nthreads], z);
        }
        for (; i < n4; i += nthreads) __stcs(&energy4[i], z);
        return;
    }

    // ---- scan CTA (one class) ----------------------------------------------
    extern __shared__ unsigned int sm_mask[];               // IMG_H*WPR words
    __shared__ float sp[MAXN];
    __shared__ int   sord[MAXN];
    __shared__ int   scls[MAXN];
    __shared__ int   s_list[MAXN];
    __shared__ int   pf[MAXN];
    __shared__ int   s_k, s_ticket;
    __shared__ int   s_gx0[16], s_gx1[16], s_gy0[16], s_gy1[16];
    __shared__ int   s_ext[4];
    __shared__ int   s_msum, s_ovl, s_keep;
    __shared__ float lg[MM * MM];
    __shared__ float2 s_cx[BOXMAX];

    int c = blockIdx.x;
    int t = threadIdx.x;
    int warp = t >> 5;
    int lane = t & 31;
    int nwarps = blockDim.x >> 5;

    // self-staging sort + class per sorted slot
    if (t < N) sp[t] = prob[t];
    __syncthreads();
    if (t < N) {
        float pi = sp[t];
        int r = 0;
        for (int j = 0; j < N; j++) {
            float pj = sp[j];
            r += (pj > pi) || (pj == pi && j < t);
        }
        sord[r] = t;
        scls[r] = clsidx[t] - 1;
    }
    __syncthreads();

    if (t == 0) {
        int k = 0;
        for (int i = 0; i < N; i++)
            if (scls[i] == c) s_list[k++] = i;
        s_k = k;
    }
    __syncthreads();
    int k = s_k;

    if (k > 0) {
        // stage clipped geometry (first 16), union rect for mask zero (k>=2)
        int kc = min(k, 16);
        if (t < kc) {
            int i = s_list[t];
            float4 rb = reinterpret_cast<const float4*>(rois)[sord[i]];
            s_gx0[t] = max((int)rb.x, 0);
            s_gx1[t] = min((int)rb.z + 1, IMG_W);
            s_gy0[t] = max((int)rb.y, 0);
            s_gy1[t] = min((int)rb.w + 1, IMG_H);
        }
        __syncthreads();
        if (k >= 2) {
            if (t == 0) {
                int ux0 = IMG_W, ux1 = 0, uy0 = IMG_H, uy1 = 0;
                for (int j = 0; j < kc; j++) {
                    if (s_gx0[j] < s_gx1[j] && s_gy0[j] < s_gy1[j]) {
                        ux0 = min(ux0, s_gx0[j]); ux1 = max(ux1, s_gx1[j]);
                        uy0 = min(uy0, s_gy0[j]); uy1 = max(uy1, s_gy1[j]);
                    }
                }
                if (k > 16) { ux0 = 0; ux1 = IMG_W; uy0 = 0; uy1 = IMG_H; }
                s_ext[0] = ux0 >> 5;
                s_ext[1] = (ux1 + 31) >> 5;
                s_ext[2] = uy0;
                s_ext[3] = uy1;
            }
            __syncthreads();
            int uw0 = s_ext[0], uw1 = s_ext[1], uy0 = s_ext[2], uy1 = s_ext[3];
            int unw = max(uw1 - uw0, 0);
            int unrows = max(uy1 - uy0, 0);
            for (int w = t; w < unw * unrows; w += blockDim.x) {
                int r = w / unw;
                sm_mask[(uy0 + r) * WPR + uw0 + (w - r * unw)] = 0u;
            }
            __syncthreads();
        }

        bool mask_ne = false;

        for (int j = 0; j < k; j++) {
            int i = s_list[j];
            int o = sord[i];

            int xs0, xs1, ys0, ys1;
            if (j < 16) {
                xs0 = s_gx0[j]; xs1 = s_gx1[j]; ys0 = s_gy0[j]; ys1 = s_gy1[j];
            } else {
                float4 rb = reinterpret_cast<const float4*>(rois)[o];
                xs0 = max((int)rb.x, 0); xs1 = min((int)rb.z + 1, IMG_W);
                ys0 = max((int)rb.y, 0); ys1 = min((int)rb.w + 1, IMG_H);
            }
            int bw = xs1 - xs0, bh = ys1 - ys0;
            if (bw <= 0 || bh <= 0) {
                if (t == 0) g_keep[i] = 0;
                __syncthreads();
                continue;
            }

            // load logit + original box (unclipped) for sampling transform
            float4 rb = reinterpret_cast<const float4*>(rois)[o];
            int x0 = (int)rb.x, y0 = (int)rb.y, x1 = (int)rb.z, y1 = (int)rb.w;
            const float* lp = mask_prob + (long long)o * (MM * MM);
            for (int u = t; u < MM * MM; u += blockDim.x) lg[u] = lp[u];
            if (t == 0) { s_msum = 0; s_ovl = 0; }

            float wv = fmaxf((float)(x1 - x0 + 1), 1.0f);
            float hv = fmaxf((float)(y1 - y0 + 1), 1.0f);
            float scx = 28.0f / wv, scy = 28.0f / hv;

            bool pre = (bw <= BOXMAX);
            if (pre) {
                for (int u = t; u < bw; u += blockDim.x) {
                    float sx = fminf(fmaxf(((float)(xs0 + u) - (float)x0 + 0.5f) * scx - 0.5f, 0.0f), 27.0f);
                    int ix0 = (int)sx;
                    s_cx[u] = make_float2(sx - (float)ix0, __int_as_float(ix0));
                }
            }
            __syncthreads();

            int xw0 = xs0 >> 5, xw1 = (xs1 + 31) >> 5;

            // ---- pass A: count msum and overlap-vs-mask ---------------------
            int lm = 0, lo = 0;
            for (int r = warp; r < bh; r += nwarps) {
                int y = ys0 + r;
                float sy = fminf(fmaxf(((float)y - (float)y0 + 0.5f) * scy - 0.5f, 0.0f), 27.0f);
                int iy0 = (int)sy;
                int iy1 = min(iy0 + 1, MM - 1);
                float fy = sy - (float)iy0;
                int ll = min(lane, MM - 1);
                float r0v = lg[iy0 * MM + ll];
                float r1v = lg[iy1 * MM + ll];
                for (int xw = xw0; xw < xw1; xw++) {
                    int x = (xw << 5) + lane;
                    bool inb = (x >= xs0) && (x < xs1);
                    float val;
                    if (pre) {
                        float2 cf = s_cx[inb ? (x - xs0) : 0];
                        float fx = cf.x;
                        int ix0 = __float_as_int(cf.y);
                        int ix1 = min(ix0 + 1, MM - 1);
                        float v00 = __shfl_sync(0xffffffffu, r0v, ix0);
                        float v01 = __shfl_sync(0xffffffffu, r0v, ix1);
                        float v10 = __shfl_sync(0xffffffffu, r1v, ix0);
                        float v11 = __shfl_sync(0xffffffffu, r1v, ix1);
                        val = (1.0f - fy) * ((1.0f - fx) * v00 + fx * v01)
                            +         fy  * ((1.0f - fx) * v10 + fx * v11);
                    } else {
                        float sx = fminf(fmaxf(((float)x - (float)x0 + 0.5f) * scx - 0.5f, 0.0f), 27.0f);
                        val = bilin_ref(lg, sx, sy);
                    }
                    unsigned int bits = __ballot_sync(0xffffffffu, inb && (val > 0.0f));
                    if (lane == 0) {
                        lm += __popc(bits);
                        if (mask_ne) lo += __popc(bits & sm_mask[y * WPR + xw]);
                    }
                }
            }
            if (lane == 0) {
                if (lm) atomicAdd(&s_msum, lm);
                if (lo) atomicAdd(&s_ovl, lo);
            }
            __syncthreads();

            if (t == 0) {
                int msum = s_msum;
                int kp = (msum > 0) && ((float)s_ovl <= 0.3f * (float)msum);
                s_keep = kp;
                g_keep[i] = kp;
            }
            __syncthreads();

            // ---- pass B: merge into class mask ------------------------------
            if (s_keep && j < k - 1) {
                for (int r = warp; r < bh; r += nwarps) {
                    int y = ys0 + r;
                    float sy = fminf(fmaxf(((float)y - (float)y0 + 0.5f) * scy - 0.5f, 0.0f), 27.0f);
                    int iy0 = (int)sy;
                    int iy1 = min(iy0 + 1, MM - 1);
                    float fy = sy - (float)iy0;
                    int ll = min(lane, MM - 1);
                    float r0v = lg[iy0 * MM + ll];
                    float r1v = lg[iy1 * MM + ll];
                    for (int xw = xw0; xw < xw1; xw++) {
                        int x = (xw << 5) + lane;
                        bool inb = (x >= xs0) && (x < xs1);
                        float val;
                        if (pre) {
                            float2 cf = s_cx[inb ? (x - xs0) : 0];
                            float fx = cf.x;
                            int ix0 = __float_as_int(cf.y);
                            int ix1 = min(ix0 + 1, MM - 1);
                            float v00 = __shfl_sync(0xffffffffu, r0v, ix0);
                            float v01 = __shfl_sync(0xffffffffu, r0v, ix1);
                            float v10 = __shfl_sync(0xffffffffu, r1v, ix0);
                            float v11 = __shfl_sync(0xffffffffu, r1v, ix1);
                            val = (1.0f - fy) * ((1.0f - fx) * v00 + fx * v01)
                                +         fy  * ((1.0f - fx) * v10 + fx * v11);
                        } else {
                            float sx = fminf(fmaxf(((float)x - (float)x0 + 0.5f) * scx - 0.5f, 0.0f), 27.0f);
                            val = bilin_ref(lg, sx, sy);
                        }
                        unsigned int bits = __ballot_sync(0xffffffffu, inb && (val > 0.0f));
                        if (lane == 0 && bits)
                            sm_mask[y * WPR + xw] |= bits;   // unique (y,xw) per warp
                    }
                }
                mask_ne = true;
            }
            __syncthreads();
        }
    }

    // ---- arrival ticket; last scan CTA compacts -----------------------------
    __syncthreads();
    if (t == 0) {
        __threadfence();                       // publish g_keep
        s_ticket = atomicAdd(&g_done, 1);
    }
    __syncthreads();
    if (s_ticket != NCLS - 1) return;

    __threadfence();                           // acquire all g_keep
    int kv = (t < N) ? g_keep[t] : 0;
    if (t < MAXN) pf[t] = kv;
    __syncthreads();
    #pragma unroll
    for (int off = 1; off < MAXN; off <<= 1) {
        int v = (t < MAXN && t >= off) ? pf[t - off] : 0;
        __syncthreads();
        if (t < MAXN) pf[t] += v;
        __syncthreads();
    }
    int nk = pf[N - 1];
    if (t < N) {
        if (kv) {
            g_po[pf[t] - 1] = sord[t];
            if (has_keep) out_keep[pf[t] - 1] = (float)sord[t];
        }
        if (has_keep && t >= nk) out_keep[t] = -1.0f;
    }
    if (t == 0) {
        g_nk = nk;
        g_done = 0;                            // reset for next replay
        __threadfence();
    }
}

// ---------------------------------------------------------------------------
// grid (N, NSPLIT): pure paste, slot table precomputed by k_main.
__global__ __launch_bounds__(256) void k_paste(const float* __restrict__ rois,
                                               const float* __restrict__ mask_prob,
                                               float* __restrict__ energy) {
    int slot = blockIdx.x;
    if (slot >= g_nk) return;
    int o = g_po[slot];

    __shared__ float lg[MM * MM];
    __shared__ float2 s_cx[BOXMAX];

    int t = threadIdx.x;
    float4 rb = reinterpret_cast<const float4*>(rois)[o];
    int x0 = (int)rb.x, y0 = (int)rb.y, x1 = (int)rb.z, y1 = (int)rb.w;
    int xs0 = max(x0, 0), xs1 = min(x1 + 1, IMG_W);
    int ys0 = max(y0, 0), ys1 = min(y1 + 1, IMG_H);
    int bw = xs1 - xs0, bh = ys1 - ys0;
    if (bw <= 0 || bh <= 0) return;

    const float* lp = mask_prob + (long long)o * (MM * MM);
    for (int u = t; u < MM * MM; u += blockDim.x) lg[u] = lp[u];

    float wv = fmaxf((float)(x1 - x0 + 1), 1.0f);
    float hv = fmaxf((float)(y1 - y0 + 1), 1.0f);
    float scx = 28.0f / wv, scy = 28.0f / hv;

    bool pre = (bw <= BOXMAX);
    if (pre) {
        for (int u = t; u < bw; u += blockDim.x) {
            float sx = fminf(fmaxf(((float)(xs0 + u) - (float)x0 + 0.5f) * scx - 0.5f, 0.0f), 27.0f);
            int ix0 = (int)sx;
            s_cx[u] = make_float2(sx - (float)ix0, __int_as_float(ix0));
        }
    }
    __syncthreads();

    int chunk = (bh + NSPLIT - 1) / NSPLIT;
    int ry0   = blockIdx.y * chunk;
    int rows  = min(chunk, bh - ry0);
    if (rows <= 0) return;

    int xw0 = xs0 >> 5, xw1 = (xs1 + 31) >> 5;
    int warp = t >> 5;
    int lane = t & 31;
    int nwarps = blockDim.x >> 5;

    float* base = energy + (long long)slot * IMG_H * IMG_W;

    for (int r = warp; r < rows; r += nwarps) {
        int ry = ry0 + r;
        int y  = ys0 + ry;
        float sy = fminf(fmaxf(((float)y - (float)y0 + 0.5f) * scy - 0.5f, 0.0f), 27.0f);
        int iy0 = (int)sy;
        int iy1 = min(iy0 + 1, MM - 1);
        float fy = sy - (float)iy0;
        int ll = min(lane, MM - 1);
        float r0v = lg[iy0 * MM + ll];
        float r1v = lg[iy1 * MM + ll];
        float* rowp = base + y * IMG_W;

        for (int xw = xw0; xw < xw1; xw++) {
            int x = (xw << 5) + lane;
            bool inb = (x >= xs0) && (x < xs1);
            float val;
            if (pre) {
                float2 cf = s_cx[inb ? (x - xs0) : 0];
                float fx = cf.x;
                int ix0 = __float_as_int(cf.y);
                int ix1 = min(ix0 + 1, MM - 1);
                float v00 = __shfl_sync(0xffffffffu, r0v, ix0);
                float v01 = __shfl_sync(0xffffffffu, r0v, ix1);
                float v10 = __shfl_sync(0xffffffffu, r1v, ix0);
                float v11 = __shfl_sync(0xffffffffu, r1v, ix1);
                val = (1.0f - fy) * ((1.0f - fx) * v00 + fx * v01)
                    +         fy  * ((1.0f - fx) * v10 + fx * v11);
            } else {
                float sx = fminf(fmaxf(((float)x - (float)x0 + 0.5f) * scx - 0.5f, 0.0f), 27.0f);
                val = bilin_ref(lg, sx, sy);
            }
            if (inb) rowp[x] = val;
        }
    }
}

// ---------------------------------------------------------------------------
extern "C" void kernel_launch(void* const* d_in, const int* in_sizes, int n_in,
                              void* d_out, int out_size) {
    const float* rois  = (const float*)d_in[0];
    const float* prob  = (const float*)d_in[1];
    const float* mp    = (const float*)d_in[2];
    const int*   cidx  = (const int*)d_in[3];

    int N = in_sizes[1];
    if (N > MAXN) N = MAXN;

    float* out = (float*)d_out;
    long long HW = (long long)IMG_H * IMG_W;
    int has_keep = ((long long)out_size == (long long)N + (long long)N * HW) ? 1 : 0;
    float* energy = out + (has_keep ? N : 0);
    long long n4 = ((long long)N * HW) / 4;

    static bool attr_set = false;
    if (!attr_set) {
        cudaFuncSetAttribute(k_main, cudaFuncAttributeMaxDynamicSharedMemorySize,
                             CMASK_BYTES);
        attr_set = true;
    }

    k_main<<<NCLS + NW_ZERO, 256, CMASK_BYTES>>>(rois, prob, cidx, mp, out,
                                                 (float4*)energy, n4, N, has_keep);
    k_paste<<<dim3(N, NSPLIT), 256>>>(rois, mp, energy);
}

// round 13
// speedup vs baseline: 2.3414x; 2.3414x over previous
#include <cuda_runtime.h>

// ---------------------------------------------------------------------------
// MaskRemoval — R13: R11 structure (proven 84.5us) + paste split 8->16.
//   k_bits  : grid (N,24). y%3<2 zero-writer (2:1 interleave), y%3==2 raster.
//   k_scan  : grid (NCLS); last-CTA (ticket) compaction -> g_po/g_nk/keep_inds.
//   k_paste : grid (N,16). slot -> g_po[slot]; pure bilinear paste.
// ---------------------------------------------------------------------------

#define MAXN   128
#define NCLS   80
#define MM     28
#define IMG_H  800
#define IMG_W  800
#define WPR    25                      // 800/32 words per image row
#define BOXMAX 384
#define NSPLIT 8                       // raster y-slices per ROI (k_bits)
#define PSPLIT 16                      // paste y-slices per ROI (k_paste)
#define ZSPLIT 16                      // zero-writer CTA columns
#define YDIM   (ZSPLIT + NSPLIT)       // 24
#define BITSW  8192                    // words of bit-scratch per ROI
#define CMASK_BYTES (IMG_H * WPR * 4)  // 80000 B dynamic smem for k_scan

__device__ int g_keep[MAXN];
__device__ int g_msumP[MAXN][NSPLIT];            // per-slice popcounts
__device__ unsigned int g_bits[MAXN][BITSW];     // 4 MB ROI bit rasters
__device__ int g_done = 0;                       // scan arrival ticket
__device__ int g_po[MAXN];                       // slot -> original roi idx
__device__ int g_nk;                             // number of kept slots

// exact reference bilinear form (keep decision thresholds on val>0)
__device__ __forceinline__ float bilin_ref(const float* lg, float sx, float sy) {
    int ix0 = (int)sx;
    int iy0 = (int)sy;
    int ix1 = min(ix0 + 1, MM - 1);
    int iy1 = min(iy0 + 1, MM - 1);
    float fx = sx - (float)ix0;
    float fy = sy - (float)iy0;
    float v00 = lg[iy0 * MM + ix0], v01 = lg[iy0 * MM + ix1];
    float v10 = lg[iy1 * MM + ix0], v11 = lg[iy1 * MM + ix1];
    return (1.0f - fy) * ((1.0f - fx) * v00 + fx * v01)
         +         fy  * ((1.0f - fx) * v10 + fx * v11);
}

// stable descending rank sort into smem: sord[rank] = original index
__device__ __forceinline__ void stage_sort(const float* __restrict__ prob,
                                           int N, float* sp, int* sord) {
    int t = threadIdx.x;
    if (t < N) sp[t] = prob[t];
    __syncthreads();
    if (t < N) {
        float pi = sp[t];
        int r = 0;
        for (int j = 0; j < N; j++) {
            float pj = sp[j];
            r += (pj > pi) || (pj == pi && j < t);
        }
        sord[r] = t;
    }
    __syncthreads();
}

// ---------------------------------------------------------------------------
// grid (N, YDIM): role interleaved 2:1 in blockIdx.y (dispatch order).
__global__ __launch_bounds__(256) void k_bits(const float* __restrict__ rois,
                                              const float* __restrict__ prob,
                                              const float* __restrict__ mask_prob,
                                              float4* __restrict__ energy4,
                                              long long n4, int N) {
    int ymod = blockIdx.y % 3;
    if (ymod != 2) {
        int widx = (blockIdx.y / 3) * 2 + ymod;
        long long wid = (long long)blockIdx.x + (long long)N * widx;
        long long nthreads = (long long)N * ZSPLIT * blockDim.x;
        long long i = wid * blockDim.x + threadIdx.x;
        float4 z = make_float4(0.f, 0.f, 0.f, 0.f);
        long long s4 = 4 * nthreads;
        for (; i + 3 * nthreads < n4; i += s4) {
            __stcs(&energy4[i], z);
            __stcs(&energy4[i + nthreads], z);
            __stcs(&energy4[i + 2 * nthreads], z);
            __stcs(&energy4[i + 3 * nthreads], z);
        }
        for (; i < n4; i += nthreads) __stcs(&energy4[i], z);
        return;
    }
    int slice = blockIdx.y / 3;        // 0..7

    __shared__ float sp[MAXN];
    __shared__ int   sord[MAXN];
    __shared__ float lg[MM * MM];
    __shared__ float2 s_cx[BOXMAX];
    __shared__ int   s_cnt;

    int i = blockIdx.x;
    if (i >= N) return;
    stage_sort(prob, N, sp, sord);

    int o = sord[i];
    float4 rb = reinterpret_cast<const float4*>(rois)[o];
    int x0 = (int)rb.x, y0 = (int)rb.y, x1 = (int)rb.z, y1 = (int)rb.w;
    int xs0 = max(x0, 0), xs1 = min(x1 + 1, IMG_W);
    int ys0 = max(y0, 0), ys1 = min(y1 + 1, IMG_H);
    int bw = xs1 - xs0, bh = ys1 - ys0;
    if (bw <= 0 || bh <= 0) return;        // g_msumP slot never written => 0

    if (threadIdx.x == 0) s_cnt = 0;
    const float* lp = mask_prob + (long long)o * (MM * MM);
    for (int t = threadIdx.x; t < MM * MM; t += blockDim.x) lg[t] = lp[t];

    float wv = fmaxf((float)(x1 - x0 + 1), 1.0f);
    float hv = fmaxf((float)(y1 - y0 + 1), 1.0f);
    float scx = 28.0f / wv, scy = 28.0f / hv;

    bool pre = (bw <= BOXMAX);
    if (pre) {
        for (int t = threadIdx.x; t < bw; t += blockDim.x) {
            float sx = fminf(fmaxf(((float)(xs0 + t) - (float)x0 + 0.5f) * scx - 0.5f, 0.0f), 27.0f);
            int ix0 = (int)sx;
            s_cx[t] = make_float2(sx - (float)ix0, __int_as_float(ix0));
        }
    }
    __syncthreads();

    int chunk = (bh + NSPLIT - 1) / NSPLIT;
    int ry0   = slice * chunk;
    int rows  = min(chunk, bh - ry0);
    if (rows <= 0) return;

    int xw0 = xs0 >> 5, xw1 = (xs1 + 31) >> 5;
    int nwx = xw1 - xw0;
    bool fits = (nwx * bh <= BITSW);

    int warp = threadIdx.x >> 5;
    int lane = threadIdx.x & 31;
    int nwarps = blockDim.x >> 5;
    int lm = 0;

    for (int r = warp; r < rows; r += nwarps) {
        int ry = ry0 + r;
        int y  = ys0 + ry;
        float sy = fminf(fmaxf(((float)y - (float)y0 + 0.5f) * scy - 0.5f, 0.0f), 27.0f);
        int iy0 = (int)sy;
        int iy1 = min(iy0 + 1, MM - 1);
        float fy = sy - (float)iy0;
        int ll = min(lane, MM - 1);
        float r0v = lg[iy0 * MM + ll];
        float r1v = lg[iy1 * MM + ll];

        unsigned int* dst = fits ? &g_bits[i][ry * nwx] : nullptr;
        for (int xw = xw0; xw < xw1; xw++) {
            int x = (xw << 5) + lane;
            bool inb = (x >= xs0) && (x < xs1);
            float val;
            if (pre) {
                float2 cf = s_cx[inb ? (x - xs0) : 0];
                float fx = cf.x;
                int ix0 = __float_as_int(cf.y);
                int ix1 = min(ix0 + 1, MM - 1);
                float v00 = __shfl_sync(0xffffffffu, r0v, ix0);
                float v01 = __shfl_sync(0xffffffffu, r0v, ix1);
                float v10 = __shfl_sync(0xffffffffu, r1v, ix0);
                float v11 = __shfl_sync(0xffffffffu, r1v, ix1);
                val = (1.0f - fy) * ((1.0f - fx) * v00 + fx * v01)
                    +         fy  * ((1.0f - fx) * v10 + fx * v11);
            } else {
                float sx = fminf(fmaxf(((float)x - (float)x0 + 0.5f) * scx - 0.5f, 0.0f), 27.0f);
                val = bilin_ref(lg, sx, sy);
            }
            bool on = inb && (val > 0.0f);
            unsigned int bits = __ballot_sync(0xffffffffu, on);
            if (lane == 0) {
                if (dst) dst[xw - xw0] = bits;
                lm += __popc(bits);
            }
        }
    }
    if (lane == 0 && lm) atomicAdd(&s_cnt, lm);
    __syncthreads();
    if (threadIdx.x == 0) g_msumP[i][slice] = s_cnt;
}

// ---------------------------------------------------------------------------
// Per-class suppression; last-arriving CTA compacts slots + writes keep_inds.
__global__ __launch_bounds__(256) void k_scan(const float* __restrict__ rois,
                                              const float* __restrict__ prob,
                                              const int*   __restrict__ clsidx,
                                              const float* __restrict__ mask_prob,
                                              float* __restrict__ out_keep,
                                              int N, int has_keep) {
    extern __shared__ unsigned int sm_mask[];               // IMG_H*WPR words
    __shared__ float sp[MAXN];
    __shared__ int   sord[MAXN];
    __shared__ int   scls[MAXN];
    __shared__ int   s_list[MAXN];
    __shared__ int   pf[MAXN];
    __shared__ int   s_k, s_ticket;
    __shared__ int   s_gx0[16], s_gx1[16], s_gy0[16], s_gy1[16];
    __shared__ int   s_ext[4];
    __shared__ int   s_ovl, s_keep;
    __shared__ float lg[MM * MM];

    int c = blockIdx.x;
    int t = threadIdx.x;

    if (t < N) sp[t] = prob[t];
    __syncthreads();
    if (t < N) {
        float pi = sp[t];
        int r = 0;
        for (int j = 0; j < N; j++) {
            float pj = sp[j];
            r += (pj > pi) || (pj == pi && j < t);
        }
        sord[r] = t;
        scls[r] = clsidx[t] - 1;
    }
    __syncthreads();

    if (t == 0) {
        int k = 0;
        for (int i = 0; i < N; i++)
            if (scls[i] == c) s_list[k++] = i;
        s_k = k;
    }
    __syncthreads();
    int k = s_k;

    if (k == 1) {
        if (t == 0) {
            int i = s_list[0];
            int msum = 0;
            #pragma unroll
            for (int u = 0; u < NSPLIT; u++) msum += g_msumP[i][u];
            g_keep[i] = (msum > 0);
        }
    } else if (k >= 2) {
        int kc = min(k, 16);
        if (t < kc) {
            int i = s_list[t];
            float4 rb = reinterpret_cast<const float4*>(rois)[sord[i]];
            s_gx0[t] = max((int)rb.x, 0);
            s_gx1[t] = min((int)rb.z + 1, IMG_W);
            s_gy0[t] = max((int)rb.y, 0);
            s_gy1[t] = min((int)rb.w + 1, IMG_H);
        }
        __syncthreads();
        if (t == 0) {
            int ux0 = IMG_W, ux1 = 0, uy0 = IMG_H, uy1 = 0;
            for (int j = 0; j < kc; j++) {
                if (s_gx0[j] < s_gx1[j] && s_gy0[j] < s_gy1[j]) {
                    ux0 = min(ux0, s_gx0[j]); ux1 = max(ux1, s_gx1[j]);
                    uy0 = min(uy0, s_gy0[j]); uy1 = max(uy1, s_gy1[j]);
                }
            }
            if (k > 16) { ux0 = 0; ux1 = IMG_W; uy0 = 0; uy1 = IMG_H; }
            s_ext[0] = ux0 >> 5;
            s_ext[1] = (ux1 + 31) >> 5;
            s_ext[2] = uy0;
            s_ext[3] = uy1;
        }
        __syncthreads();
        int uw0 = s_ext[0], uw1 = s_ext[1], uy0 = s_ext[2], uy1 = s_ext[3];
        int unw = max(uw1 - uw0, 0);
        int unrows = max(uy1 - uy0, 0);

        for (int w = t; w < unw * unrows; w += blockDim.x) {
            int r = w / unw;
            sm_mask[(uy0 + r) * WPR + uw0 + (w - r * unw)] = 0u;
        }
        __syncthreads();

        bool mask_ne = false;

        for (int j = 0; j < k; j++) {
            int i = s_list[j];
            int msum = 0;
            #pragma unroll
            for (int u = 0; u < NSPLIT; u++) msum += g_msumP[i][u];
            if (msum == 0) { if (t == 0) g_keep[i] = 0; continue; }

            int xs0, xs1, ys0, ys1;
            if (j < 16) {
                xs0 = s_gx0[j]; xs1 = s_gx1[j]; ys0 = s_gy0[j]; ys1 = s_gy1[j];
            } else {
                float4 rb = reinterpret_cast<const float4*>(rois)[sord[i]];
                xs0 = max((int)rb.x, 0); xs1 = min((int)rb.z + 1, IMG_W);
                ys0 = max((int)rb.y, 0); ys1 = min((int)rb.w + 1, IMG_H);
            }
            int bh = ys1 - ys0;
            int xw0 = xs0 >> 5, xw1 = (xs1 + 31) >> 5;
            int nwx = xw1 - xw0;
            int total = nwx * bh;
            bool fits = (total <= BITSW);

            if (t == 0) s_ovl = 0;
            __syncthreads();

            if (mask_ne) {
                int lo = 0;
                if (fits) {
                    const unsigned int* bi = g_bits[i];
                    for (int kk = t; kk < total; kk += blockDim.x) {
                        unsigned int b = bi[kk];
                        if (b) {
                            int ry = kk / nwx;
                            int xw = xw0 + (kk - ry * nwx);
                            lo += __popc(b & sm_mask[(ys0 + ry) * WPR + xw]);
                        }
                    }
                } else {
                    int o = sord[i];
                    const float* lp = mask_prob + (long long)o * (MM * MM);
                    for (int u = t; u < MM * MM; u += blockDim.x) lg[u] = lp[u];
                    __syncthreads();
                    float4 rb = reinterpret_cast<const float4*>(rois)[o];
                    int x0 = (int)rb.x, y0 = (int)rb.y, x1 = (int)rb.z, y1 = (int)rb.w;
                    float wv = fmaxf((float)(x1 - x0 + 1), 1.0f);
                    float hv = fmaxf((float)(y1 - y0 + 1), 1.0f);
                    float scx = 28.0f / wv, scy = 28.0f / hv;
                    for (int kk = t; kk < total; kk += blockDim.x) {
                        int ry = kk / nwx;
                        int y  = ys0 + ry;
                        int xw = xw0 + (kk - ry * nwx);
                        unsigned int cw = sm_mask[y * WPR + xw];
                        if (!cw) continue;
                        float sy = fminf(fmaxf(((float)y - (float)y0 + 0.5f) * scy - 0.5f, 0.0f), 27.0f);
                        int xlo2 = max(xs0, xw << 5);
                        int xhi2 = min(xs1, (xw << 5) + 32);
                        for (int x = xlo2; x < xhi2; x++) {
                            if (cw & (1u << (x & 31))) {
                                float sx = fminf(fmaxf(((float)x - (float)x0 + 0.5f) * scx - 0.5f, 0.0f), 27.0f);
                                if (bilin_ref(lg, sx, sy) > 0.0f) lo++;
                            }
                        }
                    }
                }
                #pragma unroll
                for (int off = 16; off > 0; off >>= 1)
                    lo += __shfl_down_sync(0xffffffffu, lo, off);
                if ((t & 31) == 0 && lo) atomicAdd(&s_ovl, lo);
            }
            __syncthreads();

            if (t == 0) {
                int kp = ((float)s_ovl <= 0.3f * (float)msum);
                s_keep = kp;
                g_keep[i] = kp;
            }
            __syncthreads();

            if (s_keep && j < k - 1) {
                if (fits) {
                    const unsigned int* bi = g_bits[i];
                    for (int kk = t; kk < total; kk += blockDim.x) {
                        unsigned int b = bi[kk];
                        if (b) {
                            int ry = kk / nwx;
                            int xw = xw0 + (kk - ry * nwx);
                            sm_mask[(ys0 + ry) * WPR + xw] |= b;
                        }
                    }
                } else {
                    int o = sord[i];
                    const float* lp = mask_prob + (long long)o * (MM * MM);
                    for (int u = t; u < MM * MM; u += blockDim.x) lg[u] = lp[u];
                    __syncthreads();
                    float4 rb = reinterpret_cast<const float4*>(rois)[o];
                    int x0 = (int)rb.x, y0 = (int)rb.y, x1 = (int)rb.z, y1 = (int)rb.w;
                    float wv = fmaxf((float)(x1 - x0 + 1), 1.0f);
                    float hv = fmaxf((float)(y1 - y0 + 1), 1.0f);
                    float scx = 28.0f / wv, scy = 28.0f / hv;
                    for (int kk = t; kk < total; kk += blockDim.x) {
                        int ry = kk / nwx;
                        int y  = ys0 + ry;
                        int xw = xw0 + (kk - ry * nwx);
                        float sy = fminf(fmaxf(((float)y - (float)y0 + 0.5f) * scy - 0.5f, 0.0f), 27.0f);
                        int xlo2 = max(xs0, xw << 5);
                        int xhi2 = min(xs1, (xw << 5) + 32);
                        unsigned int bits = 0u;
                        for (int x = xlo2; x < xhi2; x++) {
                            float sx = fminf(fmaxf(((float)x - (float)x0 + 0.5f) * scx - 0.5f, 0.0f), 27.0f);
                            if (bilin_ref(lg, sx, sy) > 0.0f) bits |= (1u << (x & 31));
                        }
                        if (bits) sm_mask[y * WPR + xw] |= bits;
                    }
                }
                mask_ne = true;
            }
            __syncthreads();
        }
    }

    // ---- arrival ticket; last CTA compacts ---------------------------------
    __syncthreads();
    if (t == 0) {
        __threadfence();                       // publish g_keep
        s_ticket = atomicAdd(&g_done, 1);
    }
    __syncthreads();
    if (s_ticket != gridDim.x - 1) return;

    __threadfence();                           // acquire all g_keep
    int kv = (t < N) ? g_keep[t] : 0;
    if (t < MAXN) pf[t] = kv;
    __syncthreads();
    #pragma unroll
    for (int off = 1; off < MAXN; off <<= 1) {
        int v = (t < MAXN && t >= off) ? pf[t - off] : 0;
        __syncthreads();
        if (t < MAXN) pf[t] += v;
        __syncthreads();
    }
    int nk = pf[N - 1];
    if (t < N) {
        if (kv) {
            g_po[pf[t] - 1] = sord[t];
            if (has_keep) out_keep[pf[t] - 1] = (float)sord[t];
        }
        if (has_keep && t >= nk) out_keep[t] = -1.0f;
    }
    if (t == 0) {
        g_nk = nk;
        g_done = 0;                            // reset for next replay
        __threadfence();
    }
}

// ---------------------------------------------------------------------------
// grid (N, PSPLIT): pure paste, slot table precomputed by k_scan.
__global__ __launch_bounds__(256) void k_paste(const float* __restrict__ rois,
                                               const float* __restrict__ mask_prob,
                                               float* __restrict__ energy) {
    int slot = blockIdx.x;
    if (slot >= g_nk) return;
    int o = g_po[slot];

    __shared__ float lg[MM * MM];
    __shared__ float2 s_cx[BOXMAX];

    int t = threadIdx.x;
    float4 rb = reinterpret_cast<const float4*>(rois)[o];
    int x0 = (int)rb.x, y0 = (int)rb.y, x1 = (int)rb.z, y1 = (int)rb.w;
    int xs0 = max(x0, 0), xs1 = min(x1 + 1, IMG_W);
    int ys0 = max(y0, 0), ys1 = min(y1 + 1, IMG_H);
    int bw = xs1 - xs0, bh = ys1 - ys0;
    if (bw <= 0 || bh <= 0) return;

    const float* lp = mask_prob + (long long)o * (MM * MM);
    for (int u = t; u < MM * MM; u += blockDim.x) lg[u] = lp[u];

    float wv = fmaxf((float)(x1 - x0 + 1), 1.0f);
    float hv = fmaxf((float)(y1 - y0 + 1), 1.0f);
    float scx = 28.0f / wv, scy = 28.0f / hv;

    bool pre = (bw <= BOXMAX);
    if (pre) {
        for (int u = t; u < bw; u += blockDim.x) {
            float sx = fminf(fmaxf(((float)(xs0 + u) - (float)x0 + 0.5f) * scx - 0.5f, 0.0f), 27.0f);
            int ix0 = (int)sx;
            s_cx[u] = make_float2(sx - (float)ix0, __int_as_float(ix0));
        }
    }
    __syncthreads();

    int chunk = (bh + PSPLIT - 1) / PSPLIT;
    int ry0   = blockIdx.y * chunk;
    int rows  = min(chunk, bh - ry0);
    if (rows <= 0) return;

    int xw0 = xs0 >> 5, xw1 = (xs1 + 31) >> 5;
    int warp = t >> 5;
    int lane = t & 31;
    int nwarps = blockDim.x >> 5;

    float* base = energy + (long long)slot * IMG_H * IMG_W;

    for (int r = warp; r < rows; r += nwarps) {
        int ry = ry0 + r;
        int y  = ys0 + ry;
        float sy = fminf(fmaxf(((float)y - (float)y0 + 0.5f) * scy - 0.5f, 0.0f), 27.0f);
        int iy0 = (int)sy;
        int iy1 = min(iy0 + 1, MM - 1);
        float fy = sy - (float)iy0;
        int ll = min(lane, MM - 1);
        float r0v = lg[iy0 * MM + ll];
        float r1v = lg[iy1 * MM + ll];
        float* rowp = base + y * IMG_W;

        for (int xw = xw0; xw < xw1; xw++) {
            int x = (xw << 5) + lane;
            bool inb = (x >= xs0) && (x < xs1);
            float val;
            if (pre) {
                float2 cf = s_cx[inb ? (x - xs0) : 0];
                float fx = cf.x;
                int ix0 = __float_as_int(cf.y);
                int ix1 = min(ix0 + 1, MM - 1);
                float v00 = __shfl_sync(0xffffffffu, r0v, ix0);
                float v01 = __shfl_sync(0xffffffffu, r0v, ix1);
                float v10 = __shfl_sync(0xffffffffu, r1v, ix0);
                float v11 = __shfl_sync(0xffffffffu, r1v, ix1);
                val = (1.0f - fy) * ((1.0f - fx) * v00 + fx * v01)
                    +         fy  * ((1.0f - fx) * v10 + fx * v11);
            } else {
                float sx = fminf(fmaxf(((float)x - (float)x0 + 0.5f) * scx - 0.5f, 0.0f), 27.0f);
                val = bilin_ref(lg, sx, sy);
            }
            if (inb) rowp[x] = val;
        }
    }
}

// ---------------------------------------------------------------------------
extern "C" void kernel_launch(void* const* d_in, const int* in_sizes, int n_in,
                              void* d_out, int out_size) {
    const float* rois  = (const float*)d_in[0];
    const float* prob  = (const float*)d_in[1];
    const float* mp    = (const float*)d_in[2];
    const int*   cidx  = (const int*)d_in[3];

    int N = in_sizes[1];
    if (N > MAXN) N = MAXN;

    float* out = (float*)d_out;
    long long HW = (long long)IMG_H * IMG_W;
    int has_keep = ((long long)out_size == (long long)N + (long long)N * HW) ? 1 : 0;
    float* energy = out + (has_keep ? N : 0);
    long long n4 = ((long long)N * HW) / 4;

    static bool attr_set = false;
    if (!attr_set) {
        cudaFuncSetAttribute(k_scan, cudaFuncAttributeMaxDynamicSharedMemorySize,
                             CMASK_BYTES);
        attr_set = true;
    }

    k_bits<<<dim3(N, YDIM), 256>>>(rois, prob, mp, (float4*)energy, n4, N);
    k_scan<<<NCLS, 256, CMASK_BYTES>>>(rois, prob, cidx, mp, out, N, has_keep);
    k_paste<<<dim3(N, PSPLIT), 256>>>(rois, mp, energy);
}

// round 14
// speedup vs baseline: 2.4546x; 1.0483x over previous
#include <cuda_runtime.h>

// ---------------------------------------------------------------------------
// MaskRemoval — R14: scan fused into the zero+raster launch via spin-gating.
//   k_fused : grid (NCLS + N*24), 1D.
//             bid<NCLS              -> scan CTA (spins on g_rdone, global
//                                      per-class mask in g_cmask; last ticket
//                                      CTA compacts -> g_po/g_nk/keep_inds and
//                                      resets counters for replay)
//             rest=bid-NCLS, y=rest/N, i=rest%N:
//               y%3<2  -> zero-writer (2:1 interleave, 16 columns total)
//               y%3==2 -> raster slice y/3 of sorted ROI i -> g_bits+g_msumP,
//                         then fence + g_rdone[i]++
//   k_paste : grid (N,16). slot -> g_po[slot]; pure bilinear paste.
// ---------------------------------------------------------------------------

#define MAXN   128
#define NCLS   80
#define MM     28
#define IMG_H  800
#define IMG_W  800
#define WPR    25                      // 800/32 words per image row
#define BOXMAX 384
#define NSPLIT 8                       // raster y-slices per ROI
#define PSPLIT 16                      // paste y-slices per ROI
#define ZSPLIT 16                      // zero-writer columns
#define YDIM   (ZSPLIT + NSPLIT)       // 24
#define BITSW  8192                    // words of bit-scratch per ROI

__device__ int g_keep[MAXN];
__device__ int g_msumP[MAXN][NSPLIT];            // per-slice popcounts
__device__ unsigned int g_bits[MAXN][BITSW];     // 4 MB ROI bit rasters
__device__ unsigned int g_cmask[NCLS][IMG_H * WPR];  // 6.4 MB class masks
__device__ int g_rdone[MAXN];                    // per-ROI raster completion
__device__ int g_done = 0;                       // scan arrival ticket
__device__ int g_po[MAXN];                       // slot -> original roi idx
__device__ int g_nk;                             // number of kept slots

// exact reference bilinear form (keep decision thresholds on val>0)
__device__ __forceinline__ float bilin_ref(const float* lg, float sx, float sy) {
    int ix0 = (int)sx;
    int iy0 = (int)sy;
    int ix1 = min(ix0 + 1, MM - 1);
    int iy1 = min(iy0 + 1, MM - 1);
    float fx = sx - (float)ix0;
    float fy = sy - (float)iy0;
    float v00 = lg[iy0 * MM + ix0], v01 = lg[iy0 * MM + ix1];
    float v10 = lg[iy1 * MM + ix0], v11 = lg[iy1 * MM + ix1];
    return (1.0f - fy) * ((1.0f - fx) * v00 + fx * v01)
         +         fy  * ((1.0f - fx) * v10 + fx * v11);
}

// ---------------------------------------------------------------------------
__global__ __launch_bounds__(256) void k_fused(const float* __restrict__ rois,
                                               const float* __restrict__ prob,
                                               const int*   __restrict__ clsidx,
                                               const float* __restrict__ mask_prob,
                                               float* __restrict__ out_keep,
                                               float4* __restrict__ energy4,
                                               long long n4, int N, int has_keep) {
    __shared__ float sp[MAXN];
    __shared__ int   sord[MAXN];
    __shared__ int   scls[MAXN];
    __shared__ int   s_list[MAXN];
    __shared__ int   pf[MAXN];
    __shared__ int   s_k, s_ticket;
    __shared__ int   s_gx0[16], s_gx1[16], s_gy0[16], s_gy1[16];
    __shared__ int   s_ext[4];
    __shared__ int   s_msum, s_ovl, s_keep, s_cnt;
    __shared__ float lg[MM * MM];
    __shared__ float2 s_cx[BOXMAX];

    int t = threadIdx.x;
    int warpi = t >> 5;
    int lane  = t & 31;
    int nwarps = blockDim.x >> 5;
    int bid = blockIdx.x;

    // ======================= writer / raster CTAs ===========================
    if (bid >= NCLS) {
        int rest = bid - NCLS;
        int y = rest / N;
        int i = rest - y * N;
        int ymod = y % 3;

        if (ymod != 2) {
            // ---- zero-writer ------------------------------------------------
            int widx = (y / 3) * 2 + ymod;
            long long wid = (long long)i + (long long)N * widx;
            long long nthreads = (long long)N * ZSPLIT * blockDim.x;
            long long idx = wid * blockDim.x + t;
            float4 z = make_float4(0.f, 0.f, 0.f, 0.f);
            long long s4 = 4 * nthreads;
            for (; idx + 3 * nthreads < n4; idx += s4) {
                __stcs(&energy4[idx], z);
                __stcs(&energy4[idx + nthreads], z);
                __stcs(&energy4[idx + 2 * nthreads], z);
                __stcs(&energy4[idx + 3 * nthreads], z);
            }
            for (; idx < n4; idx += nthreads) __stcs(&energy4[idx], z);
            return;
        }

        // ---- raster slice ----------------------------------------------------
        int slice = y / 3;             // 0..7
        // self-staging sort
        if (t < N) sp[t] = prob[t];
        __syncthreads();
        if (t < N) {
            float pi = sp[t];
            int r = 0;
            for (int j = 0; j < N; j++) {
                float pj = sp[j];
                r += (pj > pi) || (pj == pi && j < t);
            }
            sord[r] = t;
        }
        if (t == 0) s_cnt = 0;
        __syncthreads();

        int o = sord[i];
        float4 rb = reinterpret_cast<const float4*>(rois)[o];
        int x0 = (int)rb.x, y0 = (int)rb.y, x1 = (int)rb.z, y1 = (int)rb.w;
        int xs0 = max(x0, 0), xs1 = min(x1 + 1, IMG_W);
        int ys0 = max(y0, 0), ys1 = min(y1 + 1, IMG_H);
        int bw = xs1 - xs0, bh = ys1 - ys0;
        bool active = (bw > 0) && (bh > 0);

        float wv = fmaxf((float)(x1 - x0 + 1), 1.0f);
        float hv = fmaxf((float)(y1 - y0 + 1), 1.0f);
        float scx = 28.0f / wv, scy = 28.0f / hv;
        bool pre = active && (bw <= BOXMAX);
        int rows = 0, ry0 = 0;

        if (active) {
            const float* lp = mask_prob + (long long)o * (MM * MM);
            for (int u = t; u < MM * MM; u += blockDim.x) lg[u] = lp[u];
            if (pre) {
                for (int u = t; u < bw; u += blockDim.x) {
                    float sx = fminf(fmaxf(((float)(xs0 + u) - (float)x0 + 0.5f) * scx - 0.5f, 0.0f), 27.0f);
                    int ix0 = (int)sx;
                    s_cx[u] = make_float2(sx - (float)ix0, __int_as_float(ix0));
                }
            }
            int chunk = (bh + NSPLIT - 1) / NSPLIT;
            ry0  = slice * chunk;
            rows = min(chunk, bh - ry0);
        }
        __syncthreads();

        if (active && rows > 0) {
            int xw0 = xs0 >> 5, xw1 = (xs1 + 31) >> 5;
            int nwx = xw1 - xw0;
            bool fits = (nwx * bh <= BITSW);
            int lm = 0;
            for (int r = warpi; r < rows; r += nwarps) {
                int ry = ry0 + r;
                int yy = ys0 + ry;
                float sy = fminf(fmaxf(((float)yy - (float)y0 + 0.5f) * scy - 0.5f, 0.0f), 27.0f);
                int iy0 = (int)sy;
                int iy1 = min(iy0 + 1, MM - 1);
                float fy = sy - (float)iy0;
                int ll = min(lane, MM - 1);
                float r0v = lg[iy0 * MM + ll];
                float r1v = lg[iy1 * MM + ll];
                unsigned int* dst = fits ? &g_bits[i][ry * nwx] : nullptr;
                for (int xw = xw0; xw < xw1; xw++) {
                    int x = (xw << 5) + lane;
                    bool inb = (x >= xs0) && (x < xs1);
                    float val;
                    if (pre) {
                        float2 cf = s_cx[inb ? (x - xs0) : 0];
                        float fx = cf.x;
                        int ix0 = __float_as_int(cf.y);
                        int ix1 = min(ix0 + 1, MM - 1);
                        float v00 = __shfl_sync(0xffffffffu, r0v, ix0);
                        float v01 = __shfl_sync(0xffffffffu, r0v, ix1);
                        float v10 = __shfl_sync(0xffffffffu, r1v, ix0);
                        float v11 = __shfl_sync(0xffffffffu, r1v, ix1);
                        val = (1.0f - fy) * ((1.0f - fx) * v00 + fx * v01)
                            +         fy  * ((1.0f - fx) * v10 + fx * v11);
                    } else {
                        float sx = fminf(fmaxf(((float)x - (float)x0 + 0.5f) * scx - 0.5f, 0.0f), 27.0f);
                        val = bilin_ref(lg, sx, sy);
                    }
                    unsigned int bits = __ballot_sync(0xffffffffu, inb && (val > 0.0f));
                    if (lane == 0) {
                        if (dst) dst[xw - xw0] = bits;
                        lm += __popc(bits);
                    }
                }
            }
            if (lane == 0 && lm) atomicAdd(&s_cnt, lm);
        }
        __syncthreads();
        if (t == 0) {
            g_msumP[i][slice] = s_cnt;         // always refreshed
            __threadfence();                   // publish bits + msum
            atomicAdd(&g_rdone[i], 1);         // signal slice completion
        }
        return;
    }

    // =========================== scan CTA (one class) =======================
    int c = bid;
    unsigned int* cm = &g_cmask[c][0];

    // self-staging sort + class per sorted slot
    if (t < N) sp[t] = prob[t];
    __syncthreads();
    if (t < N) {
        float pi = sp[t];
        int r = 0;
        for (int j = 0; j < N; j++) {
            float pj = sp[j];
            r += (pj > pi) || (pj == pi && j < t);
        }
        sord[r] = t;
        scls[r] = clsidx[t] - 1;
    }
    __syncthreads();

    if (t == 0) {
        int k = 0;
        for (int i = 0; i < N; i++)
            if (scls[i] == c) s_list[k++] = i;
        s_k = k;
    }
    __syncthreads();
    int k = s_k;

    if (k > 0) {
        // gate: wait until all raster slices of this class's ROIs are done
        if (t < k) {
            int i = s_list[t];
            while (atomicAdd(&g_rdone[i], 0) < NSPLIT) { }
        }
        __syncthreads();
        __threadfence();                       // acquire raster outputs

        if (k == 1) {
            if (t == 0) {
                int i = s_list[0];
                int msum = 0;
                #pragma unroll
                for (int u = 0; u < NSPLIT; u++) msum += g_msumP[i][u];
                g_keep[i] = (msum > 0);
            }
        } else {
            int kc = min(k, 16);
            if (t < kc) {
                int i = s_list[t];
                float4 rb = reinterpret_cast<const float4*>(rois)[sord[i]];
                s_gx0[t] = max((int)rb.x, 0);
                s_gx1[t] = min((int)rb.z + 1, IMG_W);
                s_gy0[t] = max((int)rb.y, 0);
                s_gy1[t] = min((int)rb.w + 1, IMG_H);
            }
            __syncthreads();
            if (t == 0) {
                int ux0 = IMG_W, ux1 = 0, uy0 = IMG_H, uy1 = 0;
                for (int j = 0; j < kc; j++) {
                    if (s_gx0[j] < s_gx1[j] && s_gy0[j] < s_gy1[j]) {
                        ux0 = min(ux0, s_gx0[j]); ux1 = max(ux1, s_gx1[j]);
                        uy0 = min(uy0, s_gy0[j]); uy1 = max(uy1, s_gy1[j]);
                    }
                }
                if (k > 16) { ux0 = 0; ux1 = IMG_W; uy0 = 0; uy1 = IMG_H; }
                s_ext[0] = ux0 >> 5;
                s_ext[1] = (ux1 + 31) >> 5;
                s_ext[2] = uy0;
                s_ext[3] = uy1;
            }
            __syncthreads();
            int uw0 = s_ext[0], uw1 = s_ext[1], uy0 = s_ext[2], uy1 = s_ext[3];
            int unw = max(uw1 - uw0, 0);
            int unrows = max(uy1 - uy0, 0);
            for (int w = t; w < unw * unrows; w += blockDim.x) {
                int r = w / unw;
                cm[(uy0 + r) * WPR + uw0 + (w - r * unw)] = 0u;
            }
            __syncthreads();

            bool mask_ne = false;

            for (int j = 0; j < k; j++) {
                int i = s_list[j];
                int msum = 0;
                #pragma unroll
                for (int u = 0; u < NSPLIT; u++) msum += g_msumP[i][u];
                if (msum == 0) { if (t == 0) g_keep[i] = 0; continue; }

                int xs0, xs1, ys0, ys1;
                if (j < 16) {
                    xs0 = s_gx0[j]; xs1 = s_gx1[j]; ys0 = s_gy0[j]; ys1 = s_gy1[j];
                } else {
                    float4 rb = reinterpret_cast<const float4*>(rois)[sord[i]];
                    xs0 = max((int)rb.x, 0); xs1 = min((int)rb.z + 1, IMG_W);
                    ys0 = max((int)rb.y, 0); ys1 = min((int)rb.w + 1, IMG_H);
                }
                int bh = ys1 - ys0;
                int xw0 = xs0 >> 5, xw1 = (xs1 + 31) >> 5;
                int nwx = xw1 - xw0;
                int total = nwx * bh;
                bool fits = (total <= BITSW);

                if (t == 0) s_ovl = 0;
                __syncthreads();

                if (mask_ne) {
                    int lo = 0;
                    if (fits) {
                        const unsigned int* bi = g_bits[i];
                        for (int kk = t; kk < total; kk += blockDim.x) {
                            unsigned int b = bi[kk];
                            if (b) {
                                int ry = kk / nwx;
                                int xw = xw0 + (kk - ry * nwx);
                                lo += __popc(b & cm[(ys0 + ry) * WPR + xw]);
                            }
                        }
                    } else {
                        int o = sord[i];
                        const float* lp = mask_prob + (long long)o * (MM * MM);
                        for (int u = t; u < MM * MM; u += blockDim.x) lg[u] = lp[u];
                        __syncthreads();
                        float4 rb = reinterpret_cast<const float4*>(rois)[o];
                        int x0 = (int)rb.x, y0 = (int)rb.y, x1 = (int)rb.z, y1 = (int)rb.w;
                        float wv = fmaxf((float)(x1 - x0 + 1), 1.0f);
                        float hv = fmaxf((float)(y1 - y0 + 1), 1.0f);
                        float scx = 28.0f / wv, scy = 28.0f / hv;
                        for (int kk = t; kk < total; kk += blockDim.x) {
                            int ry = kk / nwx;
                            int yy = ys0 + ry;
                            int xw = xw0 + (kk - ry * nwx);
                            unsigned int cw = cm[yy * WPR + xw];
                            if (!cw) continue;
                            float sy = fminf(fmaxf(((float)yy - (float)y0 + 0.5f) * scy - 0.5f, 0.0f), 27.0f);
                            int xlo2 = max(xs0, xw << 5);
                            int xhi2 = min(xs1, (xw << 5) + 32);
                            for (int x = xlo2; x < xhi2; x++) {
                                if (cw & (1u << (x & 31))) {
                                    float sx = fminf(fmaxf(((float)x - (float)x0 + 0.5f) * scx - 0.5f, 0.0f), 27.0f);
                                    if (bilin_ref(lg, sx, sy) > 0.0f) lo++;
                                }
                            }
                        }
                    }
                    #pragma unroll
                    for (int off = 16; off > 0; off >>= 1)
                        lo += __shfl_down_sync(0xffffffffu, lo, off);
                    if ((t & 31) == 0 && lo) atomicAdd(&s_ovl, lo);
                }
                __syncthreads();

                if (t == 0) {
                    int kp = ((float)s_ovl <= 0.3f * (float)msum);
                    s_keep = kp;
                    g_keep[i] = kp;
                }
                __syncthreads();

                if (s_keep && j < k - 1) {
                    if (fits) {
                        const unsigned int* bi = g_bits[i];
                        for (int kk = t; kk < total; kk += blockDim.x) {
                            unsigned int b = bi[kk];
                            if (b) {
                                int ry = kk / nwx;
                                int xw = xw0 + (kk - ry * nwx);
                                cm[(ys0 + ry) * WPR + xw] |= b;
                            }
                        }
                    } else {
                        int o = sord[i];
                        const float* lp = mask_prob + (long long)o * (MM * MM);
                        for (int u = t; u < MM * MM; u += blockDim.x) lg[u] = lp[u];
                        __syncthreads();
                        float4 rb = reinterpret_cast<const float4*>(rois)[o];
                        int x0 = (int)rb.x, y0 = (int)rb.y, x1 = (int)rb.z, y1 = (int)rb.w;
                        float wv = fmaxf((float)(x1 - x0 + 1), 1.0f);
                        float hv = fmaxf((float)(y1 - y0 + 1), 1.0f);
                        float scx = 28.0f / wv, scy = 28.0f / hv;
                        for (int kk = t; kk < total; kk += blockDim.x) {
                            int ry = kk / nwx;
                            int yy = ys0 + ry;
                            int xw = xw0 + (kk - ry * nwx);
                            float sy = fminf(fmaxf(((float)yy - (float)y0 + 0.5f) * scy - 0.5f, 0.0f), 27.0f);
                            int xlo2 = max(xs0, xw << 5);
                            int xhi2 = min(xs1, (xw << 5) + 32);
                            unsigned int bits = 0u;
                            for (int x = xlo2; x < xhi2; x++) {
                                float sx = fminf(fmaxf(((float)x - (float)x0 + 0.5f) * scx - 0.5f, 0.0f), 27.0f);
                                if (bilin_ref(lg, sx, sy) > 0.0f) bits |= (1u << (x & 31));
                            }
                            if (bits) cm[yy * WPR + xw] |= bits;
                        }
                    }
                    mask_ne = true;
                }
                __syncthreads();
            }
        }
    }

    // ---- arrival ticket; last scan CTA compacts + resets counters ----------
    __syncthreads();
    if (t == 0) {
        __threadfence();                       // publish g_keep
        s_ticket = atomicAdd(&g_done, 1);
    }
    __syncthreads();
    if (s_ticket != NCLS - 1) return;

    __threadfence();                           // acquire all g_keep
    int kv = (t < N) ? g_keep[t] : 0;
    if (t < MAXN) pf[t] = kv;
    __syncthreads();
    #pragma unroll
    for (int off = 1; off < MAXN; off <<= 1) {
        int v = (t < MAXN && t >= off) ? pf[t - off] : 0;
        __syncthreads();
        if (t < MAXN) pf[t] += v;
        __syncthreads();
    }
    int nk = pf[N - 1];
    if (t < N) {
        if (kv) {
            g_po[pf[t] - 1] = sord[t];
            if (has_keep) out_keep[pf[t] - 1] = (float)sord[t];
        }
        if (has_keep && t >= nk) out_keep[t] = -1.0f;
    }
    // wait for ALL rasters (other classes' too) before resetting counters
    if (t < N) {
        while (atomicAdd(&g_rdone[t], 0) < NSPLIT) { }
    }
    __syncthreads();
    if (t < MAXN) g_rdone[t] = 0;
    if (t == 0) {
        g_nk = nk;
        g_done = 0;                            // reset for next replay
        __threadfence();
    }
}

// ---------------------------------------------------------------------------
// grid (N, PSPLIT): pure paste, slot table precomputed by k_fused.
__global__ __launch_bounds__(256) void k_paste(const float* __restrict__ rois,
                                               const float* __restrict__ mask_prob,
                                               float* __restrict__ energy) {
    int slot = blockIdx.x;
    if (slot >= g_nk) return;
    int o = g_po[slot];

    __shared__ float lg[MM * MM];
    __shared__ float2 s_cx[BOXMAX];

    int t = threadIdx.x;
    float4 rb = reinterpret_cast<const float4*>(rois)[o];
    int x0 = (int)rb.x, y0 = (int)rb.y, x1 = (int)rb.z, y1 = (int)rb.w;
    int xs0 = max(x0, 0), xs1 = min(x1 + 1, IMG_W);
    int ys0 = max(y0, 0), ys1 = min(y1 + 1, IMG_H);
    int bw = xs1 - xs0, bh = ys1 - ys0;
    if (bw <= 0 || bh <= 0) return;

    const float* lp = mask_prob + (long long)o * (MM * MM);
    for (int u = t; u < MM * MM; u += blockDim.x) lg[u] = lp[u];

    float wv = fmaxf((float)(x1 - x0 + 1), 1.0f);
    float hv = fmaxf((float)(y1 - y0 + 1), 1.0f);
    float scx = 28.0f / wv, scy = 28.0f / hv;

    bool pre = (bw <= BOXMAX);
    if (pre) {
        for (int u = t; u < bw; u += blockDim.x) {
            float sx = fminf(fmaxf(((float)(xs0 + u) - (float)x0 + 0.5f) * scx - 0.5f, 0.0f), 27.0f);
            int ix0 = (int)sx;
            s_cx[u] = make_float2(sx - (float)ix0, __int_as_float(ix0));
        }
    }
    __syncthreads();

    int chunk = (bh + PSPLIT - 1) / PSPLIT;
    int ry0   = blockIdx.y * chunk;
    int rows  = min(chunk, bh - ry0);
    if (rows <= 0) return;

    int xw0 = xs0 >> 5, xw1 = (xs1 + 31) >> 5;
    int warpi = t >> 5;
    int lane = t & 31;
    int nwarps = blockDim.x >> 5;

    float* base = energy + (long long)slot * IMG_H * IMG_W;

    for (int r = warpi; r < rows; r += nwarps) {
        int ry = ry0 + r;
        int y  = ys0 + ry;
        float sy = fminf(fmaxf(((float)y - (float)y0 + 0.5f) * scy - 0.5f, 0.0f), 27.0f);
        int iy0 = (int)sy;
        int iy1 = min(iy0 + 1, MM - 1);
        float fy = sy - (float)iy0;
        int ll = min(lane, MM - 1);
        float r0v = lg[iy0 * MM + ll];
        float r1v = lg[iy1 * MM + ll];
        float* rowp = base + y * IMG_W;

        for (int xw = xw0; xw < xw1; xw++) {
            int x = (xw << 5) + lane;
            bool inb = (x >= xs0) && (x < xs1);
            float val;
            if (pre) {
                float2 cf = s_cx[inb ? (x - xs0) : 0];
                float fx = cf.x;
                int ix0 = __float_as_int(cf.y);
                int ix1 = min(ix0 + 1, MM - 1);
                float v00 = __shfl_sync(0xffffffffu, r0v, ix0);
                float v01 = __shfl_sync(0xffffffffu, r0v, ix1);
                float v10 = __shfl_sync(0xffffffffu, r1v, ix0);
                float v11 = __shfl_sync(0xffffffffu, r1v, ix1);
                val = (1.0f - fy) * ((1.0f - fx) * v00 + fx * v01)
                    +         fy  * ((1.0f - fx) * v10 + fx * v11);
            } else {
                float sx = fminf(fmaxf(((float)x - (float)x0 + 0.5f) * scx - 0.5f, 0.0f), 27.0f);
                val = bilin_ref(lg, sx, sy);
            }
            if (inb) rowp[x] = val;
        }
    }
}

// ---------------------------------------------------------------------------
extern "C" void kernel_launch(void* const* d_in, const int* in_sizes, int n_in,
                              void* d_out, int out_size) {
    const float* rois  = (const float*)d_in[0];
    const float* prob  = (const float*)d_in[1];
    const float* mp    = (const float*)d_in[2];
    const int*   cidx  = (const int*)d_in[3];

    int N = in_sizes[1];
    if (N > MAXN) N = MAXN;

    float* out = (float*)d_out;
    long long HW = (long long)IMG_H * IMG_W;
    int has_keep = ((long long)out_size == (long long)N + (long long)N * HW) ? 1 : 0;
    float* energy = out + (has_keep ? N : 0);
    long long n4 = ((long long)N * HW) / 4;

    k_fused<<<NCLS + N * YDIM, 256>>>(rois, prob, cidx, mp, out,
                                      (float4*)energy, n4, N, has_keep);
    k_paste<<<dim3(N, PSPLIT), 256>>>(rois, mp, energy);
}